// round 3
// baseline (speedup 1.0000x reference)
#include <cuda_runtime.h>
#include <cstdint>
#include <cstddef>

#define BJ      8192
#define MDIM    4096
#define KDIM    4096
#define NADPT   4
#define DR      16

// scratch: pre-split T (4 MB) + pre-split B (4 MB); uint2 = (tf32_hi, tf32_lo)
__device__ uint2 g_Ts[NADPT * BJ * DR];
__device__ uint2 g_Bs[NADPT * KDIM * DR];

// ---------------------------------------------------------------------------
__device__ __forceinline__ uint2 split_tf32(float v) {
    uint2 p;
    asm("cvt.rna.tf32.f32 %0, %1;" : "=r"(p.x) : "f"(v));
    float r = v - __uint_as_float(p.x);
    asm("cvt.rna.tf32.f32 %0, %1;" : "=r"(p.y) : "f"(r));
    return p;
}

__device__ __forceinline__ void mma8(float c[4], uint32_t a0, uint32_t a1, uint32_t a2,
                                     uint32_t a3, uint32_t b0, uint32_t b1) {
    asm volatile(
        "mma.sync.aligned.m16n8k8.row.col.f32.tf32.tf32.f32 "
        "{%0,%1,%2,%3}, {%4,%5,%6,%7}, {%8,%9}, {%0,%1,%2,%3};\n"
        : "+f"(c[0]), "+f"(c[1]), "+f"(c[2]), "+f"(c[3])
        : "r"(a0), "r"(a1), "r"(a2), "r"(a3), "r"(b0), "r"(b1));
}

// 3-pass split-tf32 product: hi*hi + lo*hi + hi*lo
__device__ __forceinline__ void mma3(float c1[4], float c2[4], float c3[4],
                                     const uint2 a[4], const uint2 b[2]) {
    mma8(c1, a[0].x, a[1].x, a[2].x, a[3].x, b[0].x, b[1].x);
    mma8(c2, a[0].y, a[1].y, a[2].y, a[3].y, b[0].x, b[1].x);
    mma8(c3, a[0].x, a[1].x, a[2].x, a[3].x, b[0].y, b[1].y);
}

// ---------------------------------------------------------------------------
// prep: pre-split lora_B
// ---------------------------------------------------------------------------
__global__ void split_B_kernel(const float* __restrict__ Bm) {
    int i = blockIdx.x * 256 + threadIdx.x;
    g_Bs[i] = split_tf32(Bm[i]);
}

// ---------------------------------------------------------------------------
// Stage 1: T[bj][nd] = X[bj][m] @ Aall[nd][m]^T, nd = n*16+d (64 cols total).
// 128 CTAs x 256 thr (8 warps = 2 wm x 4 wn, warp tile 32x16), K chunks of 32.
// Elements are split to (hi,lo) ONCE by the loader into smem; mainloop is
// pure LDS.64 + mma. Epilogue writes pre-split T.
// ---------------------------------------------------------------------------
__global__ __launch_bounds__(256)
void lora_stage1(const float* __restrict__ x, const float* __restrict__ Aall) {
    __shared__ uint2 Xs[64 * 36];   // 64 rows x (32 k + pad4), 18 KB
    __shared__ uint2 As[64 * 36];

    const int tid  = threadIdx.x;
    const int lane = tid & 31;
    const int warp = tid >> 5;
    const int gid  = lane >> 2;
    const int tig  = lane & 3;
    const int wm   = warp & 1;        // 2 warps over 64 bj
    const int wn   = warp >> 1;       // 4 warps over 64 nd
    const int bj0  = blockIdx.x * 64;

    const int r0 = tid >> 3;          // 0..31 (rows r0, r0+32)
    const int c  = (tid & 7) * 4;     // k col within chunk

    const float* xp0 = x    + (size_t)(bj0 + r0)      * MDIM + c;
    const float* xp1 = x    + (size_t)(bj0 + r0 + 32) * MDIM + c;
    const float* ap0 = Aall + (size_t)(r0)            * MDIM + c;
    const float* ap1 = Aall + (size_t)(r0 + 32)       * MDIM + c;

    float acc1[2][2][4], acc2[2][2][4], acc3[2][2][4];
#pragma unroll
    for (int i = 0; i < 2; ++i)
#pragma unroll
        for (int j = 0; j < 2; ++j)
#pragma unroll
            for (int q = 0; q < 4; ++q) { acc1[i][j][q] = 0.f; acc2[i][j][q] = 0.f; acc3[i][j][q] = 0.f; }

    auto stage_store = [&](const float4& v, uint2* base) {
        uint2 u0 = split_tf32(v.x), u1 = split_tf32(v.y);
        uint2 u2 = split_tf32(v.z), u3 = split_tf32(v.w);
        *(uint4*)(base)     = make_uint4(u0.x, u0.y, u1.x, u1.y);
        *(uint4*)(base + 2) = make_uint4(u2.x, u2.y, u3.x, u3.y);
    };

    float4 xr0 = *(const float4*)xp0;
    float4 xr1 = *(const float4*)xp1;
    float4 ar0 = *(const float4*)ap0;
    float4 ar1 = *(const float4*)ap1;
    stage_store(xr0, &Xs[r0 * 36 + c]);
    stage_store(xr1, &Xs[(r0 + 32) * 36 + c]);
    stage_store(ar0, &As[r0 * 36 + c]);
    stage_store(ar1, &As[(r0 + 32) * 36 + c]);
    __syncthreads();

    for (int kc = 0; kc < MDIM; kc += 32) {
        const bool more = (kc + 32) < MDIM;
        if (more) {
            xr0 = *(const float4*)(xp0 + kc + 32);
            xr1 = *(const float4*)(xp1 + kc + 32);
            ar0 = *(const float4*)(ap0 + kc + 32);
            ar1 = *(const float4*)(ap1 + kc + 32);
        }

#pragma unroll
        for (int kk = 0; kk < 32; kk += 8) {
            uint2 a[2][4], b[2][2];
#pragma unroll
            for (int mi = 0; mi < 2; ++mi) {
                const uint2* xr = &Xs[(wm * 32 + mi * 16 + gid) * 36 + kk + tig];
                a[mi][0] = xr[0];
                a[mi][1] = xr[8 * 36];
                a[mi][2] = xr[4];
                a[mi][3] = xr[8 * 36 + 4];
            }
#pragma unroll
            for (int ni = 0; ni < 2; ++ni) {
                const uint2* br = &As[(wn * 16 + ni * 8 + gid) * 36 + kk + tig];
                b[ni][0] = br[0];
                b[ni][1] = br[4];
            }
#pragma unroll
            for (int mi = 0; mi < 2; ++mi)
#pragma unroll
                for (int ni = 0; ni < 2; ++ni)
                    mma3(acc1[mi][ni], acc2[mi][ni], acc3[mi][ni], a[mi], b[ni]);
        }
        __syncthreads();
        if (more) {
            stage_store(xr0, &Xs[r0 * 36 + c]);
            stage_store(xr1, &Xs[(r0 + 32) * 36 + c]);
            stage_store(ar0, &As[r0 * 36 + c]);
            stage_store(ar1, &As[(r0 + 32) * 36 + c]);
            __syncthreads();
        }
    }

    // epilogue: combine passes, split, write pre-split T
#pragma unroll
    for (int mi = 0; mi < 2; ++mi)
#pragma unroll
        for (int ni = 0; ni < 2; ++ni) {
            const int row = bj0 + wm * 32 + mi * 16 + gid;
            const int col = wn * 16 + ni * 8 + 2 * tig;   // nd, even
            const int n = col >> 4, d = col & 15;
            float v0 = acc1[mi][ni][0] + acc2[mi][ni][0] + acc3[mi][ni][0];
            float v1 = acc1[mi][ni][1] + acc2[mi][ni][1] + acc3[mi][ni][1];
            float v2 = acc1[mi][ni][2] + acc2[mi][ni][2] + acc3[mi][ni][2];
            float v3 = acc1[mi][ni][3] + acc2[mi][ni][3] + acc3[mi][ni][3];
            uint2 u0 = split_tf32(v0), u1 = split_tf32(v1);
            uint2 u2 = split_tf32(v2), u3 = split_tf32(v3);
            uint2* dst0 = &g_Ts[((size_t)(n * BJ) + row) * DR + d];
            uint2* dst1 = &g_Ts[((size_t)(n * BJ) + row + 8) * DR + d];
            *(uint4*)dst0 = make_uint4(u0.x, u0.y, u1.x, u1.y);
            *(uint4*)dst1 = make_uint4(u2.x, u2.y, u3.x, u3.y);
        }
}

// ---------------------------------------------------------------------------
// Stage 2: Out_n[bj][k] = T_n[bj][d] @ B_n[k][d]^T  (d = 16).
// Block 128 bj x 64 k, 8 warps = 4 wm x 2 wn, warp tile 32x32.
// All operands pre-split; mainloop has ZERO cvt — LDS.64 + mma + STG only.
// ---------------------------------------------------------------------------
__global__ __launch_bounds__(256)
void lora_stage2(float* __restrict__ out) {
    __shared__ uint2 Ts[128 * 18];  // 18 KB
    __shared__ uint2 Bs[64 * 18];   //  9 KB

    const int tid  = threadIdx.x;
    const int lane = tid & 31;
    const int warp = tid >> 5;
    const int gid  = lane >> 2;
    const int tig  = lane & 3;
    const int wn   = warp & 1;      // 2 warps over 64 k
    const int wm   = warp >> 1;     // 4 warps over 128 bj

    const int n   = blockIdx.z;
    const int bj0 = blockIdx.y * 128;
    const int k0  = blockIdx.x * 64;

    {   // load T tile (128x16 uint2) and B tile (64x16 uint2)
        const int r  = tid >> 1;            // 0..127
        const int c8 = (tid & 1) * 8;
        const uint2* src = &g_Ts[((size_t)(n * BJ) + bj0 + r) * DR + c8];
        *(uint4*)&Ts[r * 18 + c8]     = *(const uint4*)(src);
        *(uint4*)&Ts[r * 18 + c8 + 2] = *(const uint4*)(src + 2);
        *(uint4*)&Ts[r * 18 + c8 + 4] = *(const uint4*)(src + 4);
        *(uint4*)&Ts[r * 18 + c8 + 6] = *(const uint4*)(src + 6);

        const int rb = tid >> 2;            // 0..63
        const int c4 = (tid & 3) * 4;
        const uint2* bsrc = &g_Bs[((size_t)(n * KDIM) + k0 + rb) * DR + c4];
        *(uint4*)&Bs[rb * 18 + c4]     = *(const uint4*)(bsrc);
        *(uint4*)&Bs[rb * 18 + c4 + 2] = *(const uint4*)(bsrc + 2);
    }
    __syncthreads();

    float c1[2][4][4], c2[2][4][4], c3[2][4][4];
#pragma unroll
    for (int i = 0; i < 2; ++i)
#pragma unroll
        for (int j = 0; j < 4; ++j)
#pragma unroll
            for (int q = 0; q < 4; ++q) { c1[i][j][q] = 0.f; c2[i][j][q] = 0.f; c3[i][j][q] = 0.f; }

#pragma unroll
    for (int kk = 0; kk < 16; kk += 8) {
        uint2 a[2][4], b[4][2];
#pragma unroll
        for (int mi = 0; mi < 2; ++mi) {
            const uint2* tr = &Ts[(wm * 32 + mi * 16 + gid) * 18 + kk + tig];
            a[mi][0] = tr[0];
            a[mi][1] = tr[8 * 18];
            a[mi][2] = tr[4];
            a[mi][3] = tr[8 * 18 + 4];
        }
#pragma unroll
        for (int ni = 0; ni < 4; ++ni) {
            const uint2* br = &Bs[(wn * 32 + ni * 8 + gid) * 18 + kk + tig];
            b[ni][0] = br[0];
            b[ni][1] = br[4];
        }
#pragma unroll
        for (int mi = 0; mi < 2; ++mi)
#pragma unroll
            for (int ni = 0; ni < 4; ++ni)
                mma3(c1[mi][ni], c2[mi][ni], c3[mi][ni], a[mi], b[ni]);
    }

#pragma unroll
    for (int mi = 0; mi < 2; ++mi)
#pragma unroll
        for (int ni = 0; ni < 4; ++ni) {
            const int row = bj0 + wm * 32 + mi * 16 + gid;
            const int col = k0 + wn * 32 + ni * 8 + 2 * tig;
            const size_t base = ((size_t)n * BJ + row) * (size_t)KDIM + col;
            float v0 = c1[mi][ni][0] + c2[mi][ni][0] + c3[mi][ni][0];
            float v1 = c1[mi][ni][1] + c2[mi][ni][1] + c3[mi][ni][1];
            float v2 = c1[mi][ni][2] + c2[mi][ni][2] + c3[mi][ni][2];
            float v3 = c1[mi][ni][3] + c2[mi][ni][3] + c3[mi][ni][3];
            *(float2*)&out[base]            = make_float2(v0, v1);
            *(float2*)&out[base + 8 * KDIM] = make_float2(v2, v3);
        }
}

// ---------------------------------------------------------------------------
extern "C" void kernel_launch(void* const* d_in, const int* in_sizes, int n_in,
                              void* d_out, int out_size) {
    const float* x    = (const float*)d_in[0];   // [8192, 4096]
    const float* Aall = (const float*)d_in[1];   // [64, 4096]
    const float* Bm   = (const float*)d_in[2];   // [4*4096, 16]
    float* out = (float*)d_out;                  // [4, 8192, 4096]

    split_B_kernel<<<NADPT * KDIM * DR / 256, 256>>>(Bm);
    lora_stage1<<<128, 256>>>(x, Aall);
    lora_stage2<<<dim3(KDIM / 64, BJ / 128, NADPT), 256>>>(out);
}

// round 4
// speedup vs baseline: 2.0855x; 2.0855x over previous
#include <cuda_runtime.h>
#include <cuda_fp16.h>
#include <cstdint>
#include <cstddef>

#define BJ      8192
#define MDIM    4096
#define KDIM    4096
#define NADPT   4
#define DR      16

#define SCALE_F   4096.0f
#define INV_SCALE (1.0f / 4096.0f)

// pre-split T, packed half2: [n][bj][16 words] = 8 hi-pairs then 8 lo-pairs (2 MB)
__device__ uint32_t g_T[NADPT * BJ * 16];

// ---------------------------------------------------------------------------
__device__ __forceinline__ void split_h2(float a, float b, uint32_t& hi, uint32_t& lo) {
    __half2 h = __floats2half2_rn(a, b);
    float2 hf = __half22float2(h);
    __half2 l = __floats2half2_rn((a - hf.x) * SCALE_F, (b - hf.y) * SCALE_F);
    hi = *reinterpret_cast<uint32_t*>(&h);
    lo = *reinterpret_cast<uint32_t*>(&l);
}

__device__ __forceinline__ void mma16(float c[4], uint32_t a0, uint32_t a1, uint32_t a2,
                                      uint32_t a3, uint32_t b0, uint32_t b1) {
    asm volatile(
        "mma.sync.aligned.m16n8k16.row.col.f32.f16.f16.f32 "
        "{%0,%1,%2,%3}, {%4,%5,%6,%7}, {%8,%9}, {%0,%1,%2,%3};\n"
        : "+f"(c[0]), "+f"(c[1]), "+f"(c[2]), "+f"(c[3])
        : "r"(a0), "r"(a1), "r"(a2), "r"(a3), "r"(b0), "r"(b1));
}

// ---------------------------------------------------------------------------
// Stage 1: T[bj][nd] = X[bj][m] @ A[nd][m]^T   (nd = n*16+d, 64 cols)
// 128 CTAs x 256 thr. 8 warps = 2(wm) x 4(wn); warp tile 32 bj x 16 nd.
// k-chunks of 64. smem rows: 32 hi-pair words + 32 lo-pair words + pad 4.
// ---------------------------------------------------------------------------
__global__ __launch_bounds__(256)
void lora_stage1(const float* __restrict__ x, const float* __restrict__ Aall) {
    __shared__ uint32_t Xs[64 * 68];   // 17.4 KB
    __shared__ uint32_t As[64 * 68];

    const int tid  = threadIdx.x;
    const int lane = tid & 31;
    const int warp = tid >> 5;
    const int gid  = lane >> 2;
    const int tig  = lane & 3;
    const int wm   = warp & 1;        // 2 warps over 64 bj
    const int wn   = warp >> 1;       // 4 warps over 64 nd (16 each = one adapter)
    const int bj0  = blockIdx.x * 64;

    const int r0 = tid >> 2;          // 0..63
    const int c0 = (tid & 3) * 4;     // f32 col 0,4,8,12 (then +16j)

    const float* xp = x    + (size_t)(bj0 + r0) * MDIM + c0;
    const float* ap = Aall + (size_t)r0 * MDIM + c0;

    float c1[2][2][4], c2[2][2][4], c3[2][2][4];
#pragma unroll
    for (int i = 0; i < 2; ++i)
#pragma unroll
        for (int j = 0; j < 2; ++j)
#pragma unroll
            for (int q = 0; q < 4; ++q) { c1[i][j][q] = 0.f; c2[i][j][q] = 0.f; c3[i][j][q] = 0.f; }

    auto store_f4 = [&](const float4& v, int word /* pair index = f32col/2 */, uint32_t* buf) {
        uint32_t h0, l0, h1, l1;
        split_h2(v.x, v.y, h0, l0);
        split_h2(v.z, v.w, h1, l1);
        *(uint2*)&buf[r0 * 68 + word]      = make_uint2(h0, h1);
        *(uint2*)&buf[r0 * 68 + 32 + word] = make_uint2(l0, l1);
    };

    float4 xv[4], av[4];
#pragma unroll
    for (int j = 0; j < 4; ++j) { xv[j] = *(const float4*)(xp + j * 16); av[j] = *(const float4*)(ap + j * 16); }
#pragma unroll
    for (int j = 0; j < 4; ++j) { store_f4(xv[j], (c0 + j * 16) >> 1, Xs); store_f4(av[j], (c0 + j * 16) >> 1, As); }
    __syncthreads();

    for (int kc = 0; kc < MDIM; kc += 64) {
        const bool more = (kc + 64) < MDIM;
        if (more) {
#pragma unroll
            for (int j = 0; j < 4; ++j) {
                xv[j] = *(const float4*)(xp + kc + 64 + j * 16);
                av[j] = *(const float4*)(ap + kc + 64 + j * 16);
            }
        }

#pragma unroll
        for (int kki = 0; kki < 4; ++kki) {
            const int kb = kki * 8;
            uint32_t ah[2][4], al[2][4], bh[2][2], bl[2][2];
#pragma unroll
            for (int mi = 0; mi < 2; ++mi) {
                const int rr = wm * 32 + mi * 16 + gid;
                const uint32_t* p = &Xs[rr * 68 + kb + tig];
                ah[mi][0] = p[0];        ah[mi][1] = p[8 * 68];
                ah[mi][2] = p[4];        ah[mi][3] = p[8 * 68 + 4];
                al[mi][0] = p[32];       al[mi][1] = p[8 * 68 + 32];
                al[mi][2] = p[36];       al[mi][3] = p[8 * 68 + 36];
            }
#pragma unroll
            for (int ni = 0; ni < 2; ++ni) {
                const int nd = wn * 16 + ni * 8 + gid;
                const uint32_t* p = &As[nd * 68 + kb + tig];
                bh[ni][0] = p[0];  bh[ni][1] = p[4];
                bl[ni][0] = p[32]; bl[ni][1] = p[36];
            }
#pragma unroll
            for (int mi = 0; mi < 2; ++mi)
#pragma unroll
                for (int ni = 0; ni < 2; ++ni) {
                    mma16(c1[mi][ni], ah[mi][0], ah[mi][1], ah[mi][2], ah[mi][3], bh[ni][0], bh[ni][1]);
                    mma16(c2[mi][ni], al[mi][0], al[mi][1], al[mi][2], al[mi][3], bh[ni][0], bh[ni][1]);
                    mma16(c3[mi][ni], ah[mi][0], ah[mi][1], ah[mi][2], ah[mi][3], bl[ni][0], bl[ni][1]);
                }
        }
        __syncthreads();
        if (more) {
#pragma unroll
            for (int j = 0; j < 4; ++j) { store_f4(xv[j], (c0 + j * 16) >> 1, Xs); store_f4(av[j], (c0 + j * 16) >> 1, As); }
            __syncthreads();
        }
    }

    // epilogue: combine passes, split to fp16 pair, write packed T
#pragma unroll
    for (int mi = 0; mi < 2; ++mi)
#pragma unroll
        for (int ni = 0; ni < 2; ++ni) {
            const int row = bj0 + wm * 32 + mi * 16 + gid;
            const int pi  = ni * 4 + tig;               // d-pair index 0..7
            float v0 = c1[mi][ni][0] + (c2[mi][ni][0] + c3[mi][ni][0]) * INV_SCALE;
            float v1 = c1[mi][ni][1] + (c2[mi][ni][1] + c3[mi][ni][1]) * INV_SCALE;
            float v2 = c1[mi][ni][2] + (c2[mi][ni][2] + c3[mi][ni][2]) * INV_SCALE;
            float v3 = c1[mi][ni][3] + (c2[mi][ni][3] + c3[mi][ni][3]) * INV_SCALE;
            uint32_t h01, l01, h23, l23;
            split_h2(v0, v1, h01, l01);
            split_h2(v2, v3, h23, l23);
            uint32_t* d0 = &g_T[((size_t)(wn * BJ) + row) * 16];
            uint32_t* d1 = &g_T[((size_t)(wn * BJ) + row + 8) * 16];
            d0[pi] = h01; d0[8 + pi] = l01;
            d1[pi] = h23; d1[8 + pi] = l23;
        }
}

// ---------------------------------------------------------------------------
// Stage 2: Out_n[bj][k] = T_n[bj][d] @ B_n[k][d]^T   (d = 16 = one mma-K!)
// Block 128 bj x 64 k; 8 warps = 4(wm) x 2(wn); warp tile 32 x 32.
// T loaded pre-split; B split in-CTA (tiny). 24 mma/warp, zero in-loop CVT.
// ---------------------------------------------------------------------------
__global__ __launch_bounds__(256)
void lora_stage2(const float* __restrict__ Bm, float* __restrict__ out) {
    __shared__ uint32_t Ts[128 * 20];  // 10 KB
    __shared__ uint32_t Bs[64 * 20];   //  5 KB

    const int tid  = threadIdx.x;
    const int lane = tid & 31;
    const int warp = tid >> 5;
    const int gid  = lane >> 2;
    const int tig  = lane & 3;
    const int wn   = warp & 1;      // 2 warps over 64 k
    const int wm   = warp >> 1;     // 4 warps over 128 bj

    const int n   = blockIdx.z;
    const int bj0 = blockIdx.y * 128;
    const int k0  = blockIdx.x * 64;

    {   // T tile: 128 rows x 16 words
        const int r  = tid >> 1;
        const int cw = (tid & 1) * 8;
        const uint32_t* src = &g_T[((size_t)(n * BJ) + bj0 + r) * 16 + cw];
        *(uint4*)&Ts[r * 20 + cw]     = *(const uint4*)(src);
        *(uint4*)&Ts[r * 20 + cw + 4] = *(const uint4*)(src + 4);

        // B tile: 64 rows x 16 f32 -> split to pairs
        const int rb = tid >> 2;
        const int cf = (tid & 3) * 4;
        float4 bv = *(const float4*)&Bm[((size_t)(n * KDIM) + k0 + rb) * DR + cf];
        uint32_t h0, l0, h1, l1;
        split_h2(bv.x, bv.y, h0, l0);
        split_h2(bv.z, bv.w, h1, l1);
        *(uint2*)&Bs[rb * 20 + (cf >> 1)]     = make_uint2(h0, h1);
        *(uint2*)&Bs[rb * 20 + 8 + (cf >> 1)] = make_uint2(l0, l1);
    }
    __syncthreads();

    float c1[2][4][4], c2[2][4][4], c3[2][4][4];
#pragma unroll
    for (int i = 0; i < 2; ++i)
#pragma unroll
        for (int j = 0; j < 4; ++j)
#pragma unroll
            for (int q = 0; q < 4; ++q) { c1[i][j][q] = 0.f; c2[i][j][q] = 0.f; c3[i][j][q] = 0.f; }

    uint32_t ah[2][4], al[2][4];
#pragma unroll
    for (int mi = 0; mi < 2; ++mi) {
        const int r = wm * 32 + mi * 16 + gid;
        const uint32_t* p = &Ts[r * 20 + tig];
        ah[mi][0] = p[0];       ah[mi][1] = p[8 * 20];
        ah[mi][2] = p[4];       ah[mi][3] = p[8 * 20 + 4];
        al[mi][0] = p[8];       al[mi][1] = p[8 * 20 + 8];
        al[mi][2] = p[12];      al[mi][3] = p[8 * 20 + 12];
    }

#pragma unroll
    for (int ni = 0; ni < 4; ++ni) {
        const int kc = wn * 32 + ni * 8 + gid;
        const uint32_t* p = &Bs[kc * 20 + tig];
        const uint32_t bh0 = p[0], bh1 = p[4], bl0 = p[8], bl1 = p[12];
#pragma unroll
        for (int mi = 0; mi < 2; ++mi) {
            mma16(c1[mi][ni], ah[mi][0], ah[mi][1], ah[mi][2], ah[mi][3], bh0, bh1);
            mma16(c2[mi][ni], al[mi][0], al[mi][1], al[mi][2], al[mi][3], bh0, bh1);
            mma16(c3[mi][ni], ah[mi][0], ah[mi][1], ah[mi][2], ah[mi][3], bl0, bl1);
        }
    }

#pragma unroll
    for (int mi = 0; mi < 2; ++mi)
#pragma unroll
        for (int ni = 0; ni < 4; ++ni) {
            const int row = bj0 + wm * 32 + mi * 16 + gid;
            const int col = k0 + wn * 32 + ni * 8 + 2 * tig;
            const size_t base = ((size_t)n * BJ + row) * (size_t)KDIM + col;
            float v0 = c1[mi][ni][0] + (c2[mi][ni][0] + c3[mi][ni][0]) * INV_SCALE;
            float v1 = c1[mi][ni][1] + (c2[mi][ni][1] + c3[mi][ni][1]) * INV_SCALE;
            float v2 = c1[mi][ni][2] + (c2[mi][ni][2] + c3[mi][ni][2]) * INV_SCALE;
            float v3 = c1[mi][ni][3] + (c2[mi][ni][3] + c3[mi][ni][3]) * INV_SCALE;
            *(float2*)&out[base]            = make_float2(v0, v1);
            *(float2*)&out[base + 8 * KDIM] = make_float2(v2, v3);
        }
}

// ---------------------------------------------------------------------------
extern "C" void kernel_launch(void* const* d_in, const int* in_sizes, int n_in,
                              void* d_out, int out_size) {
    const float* x    = (const float*)d_in[0];   // [8192, 4096]
    const float* Aall = (const float*)d_in[1];   // [64, 4096]
    const float* Bm   = (const float*)d_in[2];   // [4*4096, 16]
    float* out = (float*)d_out;                  // [4, 8192, 4096]

    lora_stage1<<<BJ / 64, 256>>>(x, Aall);
    lora_stage2<<<dim3(KDIM / 64, BJ / 128, NADPT), 256>>>(Bm, out);
}

// round 5
// speedup vs baseline: 2.1008x; 1.0073x over previous
#include <cuda_runtime.h>
#include <cuda_fp16.h>
#include <cstdint>
#include <cstddef>

#define BJ      8192
#define MDIM    4096
#define KDIM    4096
#define NADPT   4
#define DR      16

#define SCALE_F   4096.0f
#define INV_SCALE (1.0f / 4096.0f)

// scratch: fp32 partial T (2 m-halves, 4 MB) + pre-split A (1 MB)
__device__ float    g_Tp[2][NADPT * BJ * DR];
__device__ uint32_t g_As[64 * MDIM];   // [row][chunk64][32 hi words | 32 lo words]

// ---------------------------------------------------------------------------
__device__ __forceinline__ void split_h2(float a, float b, uint32_t& hi, uint32_t& lo) {
    __half2 h = __floats2half2_rn(a, b);
    float2 hf = __half22float2(h);
    __half2 l = __floats2half2_rn((a - hf.x) * SCALE_F, (b - hf.y) * SCALE_F);
    hi = *reinterpret_cast<uint32_t*>(&h);
    lo = *reinterpret_cast<uint32_t*>(&l);
}

__device__ __forceinline__ void mma16(float c[4], uint32_t a0, uint32_t a1, uint32_t a2,
                                      uint32_t a3, uint32_t b0, uint32_t b1) {
    asm volatile(
        "mma.sync.aligned.m16n8k16.row.col.f32.f16.f16.f32 "
        "{%0,%1,%2,%3}, {%4,%5,%6,%7}, {%8,%9}, {%0,%1,%2,%3};\n"
        : "+f"(c[0]), "+f"(c[1]), "+f"(c[2]), "+f"(c[3])
        : "r"(a0), "r"(a1), "r"(a2), "r"(a3), "r"(b0), "r"(b1));
}

// ---------------------------------------------------------------------------
// prep: pre-split A[64][4096] into chunk-local hi/lo layout (matches smem)
// ---------------------------------------------------------------------------
__global__ void split_A_kernel(const float* __restrict__ Aall) {
    int i = blockIdx.x * 256 + threadIdx.x;     // one f32-pair per thread, 131072
    int r  = i >> 11;                           // row 0..63
    int k2 = i & 2047;                          // pair idx
    float2 v = *(const float2*)&Aall[(size_t)r * MDIM + 2 * k2];
    uint32_t hi, lo;
    split_h2(v.x, v.y, hi, lo);
    int chunk = k2 >> 5, wi = k2 & 31;
    uint32_t* dst = &g_As[((size_t)r * 64 + chunk) * 64];
    dst[wi]      = hi;
    dst[32 + wi] = lo;
}

// ---------------------------------------------------------------------------
// Stage 1: partial T over an M-half (2048).
// grid (128 bj-tiles, 2 m-halves) x 256 thr; 8 warps = 2(wm) x 4(wn).
// A tiles copied pre-split (no ALU); X split in-loader.
// ---------------------------------------------------------------------------
__global__ __launch_bounds__(256)
void lora_stage1(const float* __restrict__ x) {
    __shared__ uint32_t Xs[64 * 68];
    __shared__ uint32_t As[64 * 68];

    const int tid  = threadIdx.x;
    const int lane = tid & 31;
    const int warp = tid >> 5;
    const int gid  = lane >> 2;
    const int tig  = lane & 3;
    const int wm   = warp & 1;        // 2 warps over 64 bj
    const int wn   = warp >> 1;       // 4 warps over 64 nd (one adapter each)
    const int bj0  = blockIdx.x * 64;
    const int my   = blockIdx.y;
    const int m0   = my * 2048;

    const int rx = tid >> 2;          // 0..63
    const int c0 = (tid & 3) * 4;     // f32 col 0,4,8,12 (+16j)
    const int q  = tid & 3;           // A word-quarter

    const float* xp = x + (size_t)(bj0 + rx) * MDIM + m0 + c0;
    const uint32_t* ap = &g_As[((size_t)rx * 64 + my * 32) * 64 + q * 16];

    float c1[2][2][4], c2[2][2][4], c3[2][2][4];
#pragma unroll
    for (int i = 0; i < 2; ++i)
#pragma unroll
        for (int j = 0; j < 2; ++j)
#pragma unroll
            for (int k = 0; k < 4; ++k) { c1[i][j][k] = 0.f; c2[i][j][k] = 0.f; c3[i][j][k] = 0.f; }

    auto store_x = [&](const float4& v, int j) {
        uint32_t h0, l0, h1, l1;
        split_h2(v.x, v.y, h0, l0);
        split_h2(v.z, v.w, h1, l1);
        const int word = (c0 + j * 16) >> 1;
        *(uint2*)&Xs[rx * 68 + word]      = make_uint2(h0, h1);
        *(uint2*)&Xs[rx * 68 + 32 + word] = make_uint2(l0, l1);
    };

    float4 xv[4];
    uint4  av[4];
#pragma unroll
    for (int j = 0; j < 4; ++j) { xv[j] = *(const float4*)(xp + j * 16); av[j] = *(const uint4*)(ap + j * 4); }
#pragma unroll
    for (int j = 0; j < 4; ++j) { store_x(xv[j], j); *(uint4*)&As[rx * 68 + q * 16 + j * 4] = av[j]; }
    __syncthreads();

    for (int kc = 0; kc < 2048; kc += 64) {
        const bool more = (kc + 64) < 2048;
        if (more) {
#pragma unroll
            for (int j = 0; j < 4; ++j) {
                xv[j] = *(const float4*)(xp + kc + 64 + j * 16);
                av[j] = *(const uint4*)(ap + (kc / 64 + 1) * 64 + j * 4);
            }
        }

#pragma unroll
        for (int kki = 0; kki < 4; ++kki) {
            const int kb = kki * 8;
            uint32_t ah[2][4], al[2][4], bh[2][2], bl[2][2];
#pragma unroll
            for (int mi = 0; mi < 2; ++mi) {
                const uint32_t* p = &Xs[(wm * 32 + mi * 16 + gid) * 68 + kb + tig];
                ah[mi][0] = p[0];  ah[mi][1] = p[8 * 68];
                ah[mi][2] = p[4];  ah[mi][3] = p[8 * 68 + 4];
                al[mi][0] = p[32]; al[mi][1] = p[8 * 68 + 32];
                al[mi][2] = p[36]; al[mi][3] = p[8 * 68 + 36];
            }
#pragma unroll
            for (int ni = 0; ni < 2; ++ni) {
                const uint32_t* p = &As[(wn * 16 + ni * 8 + gid) * 68 + kb + tig];
                bh[ni][0] = p[0];  bh[ni][1] = p[4];
                bl[ni][0] = p[32]; bl[ni][1] = p[36];
            }
#pragma unroll
            for (int mi = 0; mi < 2; ++mi)
#pragma unroll
                for (int ni = 0; ni < 2; ++ni) {
                    mma16(c1[mi][ni], ah[mi][0], ah[mi][1], ah[mi][2], ah[mi][3], bh[ni][0], bh[ni][1]);
                    mma16(c2[mi][ni], al[mi][0], al[mi][1], al[mi][2], al[mi][3], bh[ni][0], bh[ni][1]);
                    mma16(c3[mi][ni], ah[mi][0], ah[mi][1], ah[mi][2], ah[mi][3], bl[ni][0], bl[ni][1]);
                }
        }
        __syncthreads();
        if (more) {
#pragma unroll
            for (int j = 0; j < 4; ++j) { store_x(xv[j], j); *(uint4*)&As[rx * 68 + q * 16 + j * 4] = av[j]; }
            __syncthreads();
        }
    }

    // epilogue: fp32 partials
    float* tp = g_Tp[my];
#pragma unroll
    for (int mi = 0; mi < 2; ++mi)
#pragma unroll
        for (int ni = 0; ni < 2; ++ni) {
            const int row = bj0 + wm * 32 + mi * 16 + gid;
            const int d   = ni * 8 + 2 * tig;
            float v0 = c1[mi][ni][0] + (c2[mi][ni][0] + c3[mi][ni][0]) * INV_SCALE;
            float v1 = c1[mi][ni][1] + (c2[mi][ni][1] + c3[mi][ni][1]) * INV_SCALE;
            float v2 = c1[mi][ni][2] + (c2[mi][ni][2] + c3[mi][ni][2]) * INV_SCALE;
            float v3 = c1[mi][ni][3] + (c2[mi][ni][3] + c3[mi][ni][3]) * INV_SCALE;
            float* dst = tp + ((size_t)(wn * BJ) + row) * DR + d;
            *(float2*)dst            = make_float2(v0, v1);
            *(float2*)(dst + 8 * DR) = make_float2(v2, v3);
        }
}

// ---------------------------------------------------------------------------
// Stage 2: Out_n = T_n @ B_n^T (d=16, single mma-K).
// Block 128 bj x 64 k; 8 warps = 4(wm) x 2(wn).
// B rows permuted in smem so each thread owns 4 consecutive out cols -> STG.128.
// Two 16-col groups processed sequentially to cap live registers.
// ---------------------------------------------------------------------------
__global__ __launch_bounds__(256)
void lora_stage2(const float* __restrict__ Bm, float* __restrict__ out) {
    __shared__ uint32_t Ts[128 * 20];
    __shared__ uint32_t Bs[64 * 20];

    const int tid  = threadIdx.x;
    const int lane = tid & 31;
    const int warp = tid >> 5;
    const int gid  = lane >> 2;
    const int tig  = lane & 3;
    const int wn   = warp & 1;      // 2 warps over 64 k
    const int wm   = warp >> 1;     // 4 warps over 128 bj

    const int n   = blockIdx.z;
    const int bj0 = blockIdx.y * 128;
    const int k0  = blockIdx.x * 64;

    {   // T loader: sum 2 fp32 partials, split to packed hi/lo
        const int r  = tid >> 1;
        const int cf = (tid & 1) * 8;
        const size_t base = ((size_t)(n * BJ) + bj0 + r) * DR + cf;
        float4 a0 = *(const float4*)&g_Tp[0][base];
        float4 a1 = *(const float4*)&g_Tp[0][base + 4];
        float4 b0 = *(const float4*)&g_Tp[1][base];
        float4 b1 = *(const float4*)&g_Tp[1][base + 4];
        float4 s0 = make_float4(a0.x + b0.x, a0.y + b0.y, a0.z + b0.z, a0.w + b0.w);
        float4 s1 = make_float4(a1.x + b1.x, a1.y + b1.y, a1.z + b1.z, a1.w + b1.w);
        uint32_t h0, l0, h1, l1, h2, l2, h3, l3;
        split_h2(s0.x, s0.y, h0, l0);
        split_h2(s0.z, s0.w, h1, l1);
        split_h2(s1.x, s1.y, h2, l2);
        split_h2(s1.z, s1.w, h3, l3);
        *(uint4*)&Ts[r * 20 + (cf >> 1)]     = make_uint4(h0, h1, h2, h3);
        *(uint4*)&Ts[r * 20 + 8 + (cf >> 1)] = make_uint4(l0, l1, l2, l3);

        // B loader with column permutation: global col g -> tile t=(g>>1)&1,
        // in-tile row c=(g&1)|((g>>2)<<1), so thread tig owns cols 4tig..4tig+3
        const int rb = tid >> 2;
        const int bf = (tid & 3) * 4;
        const int gg = rb & 15, pgrp = rb >> 4;
        const int prow = pgrp * 16 + ((gg >> 1) & 1) * 8 + ((gg & 1) | ((gg >> 2) << 1));
        float4 bv = *(const float4*)&Bm[((size_t)(n * KDIM) + k0 + rb) * DR + bf];
        uint32_t bh0, bl0w, bh1, bl1w;
        split_h2(bv.x, bv.y, bh0, bl0w);
        split_h2(bv.z, bv.w, bh1, bl1w);
        *(uint2*)&Bs[prow * 20 + (bf >> 1)]     = make_uint2(bh0, bh1);
        *(uint2*)&Bs[prow * 20 + 8 + (bf >> 1)] = make_uint2(bl0w, bl1w);
    }
    __syncthreads();

    uint32_t ah[2][4], al[2][4];
#pragma unroll
    for (int mi = 0; mi < 2; ++mi) {
        const uint32_t* p = &Ts[(wm * 32 + mi * 16 + gid) * 20 + tig];
        ah[mi][0] = p[0];  ah[mi][1] = p[8 * 20];
        ah[mi][2] = p[4];  ah[mi][3] = p[8 * 20 + 4];
        al[mi][0] = p[8];  al[mi][1] = p[8 * 20 + 8];
        al[mi][2] = p[12]; al[mi][3] = p[8 * 20 + 12];
    }

#pragma unroll
    for (int pi = 0; pi < 2; ++pi) {
        float c1[2][2][4], c2[2][2][4], c3[2][2][4];
#pragma unroll
        for (int i = 0; i < 2; ++i)
#pragma unroll
            for (int t = 0; t < 2; ++t)
#pragma unroll
                for (int k = 0; k < 4; ++k) { c1[i][t][k] = 0.f; c2[i][t][k] = 0.f; c3[i][t][k] = 0.f; }

#pragma unroll
        for (int t = 0; t < 2; ++t) {
            const int qrow = wn * 32 + pi * 16 + t * 8 + gid;
            const uint32_t* p = &Bs[qrow * 20 + tig];
            const uint32_t bh0 = p[0], bh1 = p[4], bl0 = p[8], bl1 = p[12];
#pragma unroll
            for (int mi = 0; mi < 2; ++mi) {
                mma16(c1[mi][t], ah[mi][0], ah[mi][1], ah[mi][2], ah[mi][3], bh0, bh1);
                mma16(c2[mi][t], al[mi][0], al[mi][1], al[mi][2], al[mi][3], bh0, bh1);
                mma16(c3[mi][t], ah[mi][0], ah[mi][1], ah[mi][2], ah[mi][3], bl0, bl1);
            }
        }

#pragma unroll
        for (int mi = 0; mi < 2; ++mi) {
            const int row = bj0 + wm * 32 + mi * 16 + gid;
            const int col = k0 + wn * 32 + pi * 16 + 4 * tig;
            const size_t base = ((size_t)n * BJ + row) * (size_t)KDIM + col;
            float4 f0, f1;
            f0.x = c1[mi][0][0] + (c2[mi][0][0] + c3[mi][0][0]) * INV_SCALE;
            f0.y = c1[mi][0][1] + (c2[mi][0][1] + c3[mi][0][1]) * INV_SCALE;
            f0.z = c1[mi][1][0] + (c2[mi][1][0] + c3[mi][1][0]) * INV_SCALE;
            f0.w = c1[mi][1][1] + (c2[mi][1][1] + c3[mi][1][1]) * INV_SCALE;
            f1.x = c1[mi][0][2] + (c2[mi][0][2] + c3[mi][0][2]) * INV_SCALE;
            f1.y = c1[mi][0][3] + (c2[mi][0][3] + c3[mi][0][3]) * INV_SCALE;
            f1.z = c1[mi][1][2] + (c2[mi][1][2] + c3[mi][1][2]) * INV_SCALE;
            f1.w = c1[mi][1][3] + (c2[mi][1][3] + c3[mi][1][3]) * INV_SCALE;
            *(float4*)&out[base]            = f0;
            *(float4*)&out[base + 8 * KDIM] = f1;
        }
    }
}

// ---------------------------------------------------------------------------
extern "C" void kernel_launch(void* const* d_in, const int* in_sizes, int n_in,
                              void* d_out, int out_size) {
    const float* x    = (const float*)d_in[0];   // [8192, 4096]
    const float* Aall = (const float*)d_in[1];   // [64, 4096]
    const float* Bm   = (const float*)d_in[2];   // [4*4096, 16]
    float* out = (float*)d_out;                  // [4, 8192, 4096]

    split_A_kernel<<<512, 256>>>(Aall);
    lora_stage1<<<dim3(128, 2), 256>>>(x);
    lora_stage2<<<dim3(KDIM / 64, BJ / 128, NADPT), 256>>>(Bm, out);
}